// round 1
// baseline (speedup 1.0000x reference)
#include <cuda_runtime.h>
#include <cstdint>

// out[r,c] = data[r,c] * (1 + dy[c%4]) + dx[c%4]
// where for group g: theta = params[0,g,0], velo = params[1,g,0],
//   ds = 0.01*velo, dx = ds*cos(theta), dy = ds*sin(theta).
// (The reference's tanh-interpolation collapses because hi = 0 -> begin = end = 0.)
//
// params layout: shape (2, 4, 120) row-major: params[0,g,0] at g*120,
//                params[1,g,0] at 480 + g*120.

static constexpr int POINTS = 120;

__global__ void foil_kernel(const float4* __restrict__ in,
                            float4* __restrict__ out,
                            const float* __restrict__ params,
                            int n4) {
    // Per-group constants (same for all threads; 8 cached scalar loads)
    float mul[4], add[4];
#pragma unroll
    for (int g = 0; g < 4; g++) {
        float theta = __ldg(&params[g * POINTS]);
        float velo  = __ldg(&params[4 * POINTS + g * POINTS]);
        float ds = velo * 0.01f;
        add[g] = ds * cosf(theta);          // dx
        mul[g] = 1.0f + ds * sinf(theta);   // 1 + dy
    }

    int i = blockIdx.x * blockDim.x + threadIdx.x;
    int stride = gridDim.x * blockDim.x;
    for (; i < n4; i += stride) {
        float4 d = in[i];
        float4 o;
        o.x = fmaf(d.x, mul[0], add[0]);
        o.y = fmaf(d.y, mul[1], add[1]);
        o.z = fmaf(d.z, mul[2], add[2]);
        o.w = fmaf(d.w, mul[3], add[3]);
        out[i] = o;
    }
}

extern "C" void kernel_launch(void* const* d_in, const int* in_sizes, int n_in,
                              void* d_out, int out_size) {
    // Inputs per metadata order: data (float32, 4096*4096), params (float32, 2*4*120)
    const float* data   = (const float*)d_in[0];
    const float* params = (const float*)d_in[1];
    // Defensive: if order is swapped, detect by size
    if (n_in >= 2 && in_sizes[0] == 2 * 4 * POINTS) {
        data   = (const float*)d_in[1];
        params = (const float*)d_in[0];
    }

    int n = out_size;          // 16,777,216 elements
    int n4 = n / 4;            // 4,194,304 float4s

    const int threads = 256;
    int blocks = (n4 + threads - 1) / threads;   // 16384 blocks -> plenty of waves
    foil_kernel<<<blocks, threads>>>((const float4*)data, (float4*)d_out, params, n4);
}

// round 3
// speedup vs baseline: 1.5636x; 1.5636x over previous
#include <cuda_runtime.h>
#include <cstdint>

// out[r,c] = data[r,c] * (1 + dy[c%4]) + dx[c%4]
// For group g: theta = params[0,g,0], velo = params[1,g,0],
//   ds = 0.01*velo, dx = ds*cos(theta), dy = ds*sin(theta).
// (Reference's tanh interpolation collapses: hi=0 -> begin=end=0 -> frame[0].)
// params layout (2,4,120) row-major: params[0,g,0] at g*120, params[1,g,0] at 480+g*120.

static constexpr int POINTS = 120;
static constexpr int ITERS  = 8;
static constexpr int TPB    = 256;

__device__ __forceinline__ unsigned long long ffma2(unsigned long long a,
                                                    unsigned long long b,
                                                    unsigned long long c) {
    unsigned long long d;
    asm("fma.rn.f32x2 %0, %1, %2, %3;" : "=l"(d) : "l"(a), "l"(b), "l"(c));
    return d;
}

__device__ __forceinline__ unsigned long long pack2(float lo, float hi) {
    unsigned long long r;
    asm("mov.b64 %0, {%1, %2};" : "=l"(r) : "f"(lo), "f"(hi));
    return r;
}

__global__ __launch_bounds__(TPB) void foil_kernel(const ulonglong2* __restrict__ in,
                                                   ulonglong2* __restrict__ out,
                                                   const float* __restrict__ params,
                                                   int n4) {
    // Per-block constants: thread 0 computes, everyone reads via shared.
    __shared__ unsigned long long s_c[4];  // mul01, mul23, add01, add23
    if (threadIdx.x == 0) {
        float mul[4], add[4];
#pragma unroll
        for (int g = 0; g < 4; g++) {
            float theta = params[g * POINTS];
            float velo  = params[4 * POINTS + g * POINTS];
            float ds = velo * 0.01f;
            add[g] = ds * cosf(theta);          // dx
            mul[g] = 1.0f + ds * sinf(theta);   // 1 + dy
        }
        s_c[0] = pack2(mul[0], mul[1]);
        s_c[1] = pack2(mul[2], mul[3]);
        s_c[2] = pack2(add[0], add[1]);
        s_c[3] = pack2(add[2], add[3]);
    }
    __syncthreads();
    const unsigned long long mul01 = s_c[0];
    const unsigned long long mul23 = s_c[1];
    const unsigned long long add01 = s_c[2];
    const unsigned long long add23 = s_c[3];

    int base = blockIdx.x * (TPB * ITERS) + threadIdx.x;

    if (base + (ITERS - 1) * TPB < n4) {
        // Fast path: no bounds checks. Front-batch the 8 loads for MLP=8.
        ulonglong2 d[ITERS];
#pragma unroll
        for (int k = 0; k < ITERS; k++)
            d[k] = in[base + k * TPB];
#pragma unroll
        for (int k = 0; k < ITERS; k++) {
            d[k].x = ffma2(d[k].x, mul01, add01);
            d[k].y = ffma2(d[k].y, mul23, add23);
            out[base + k * TPB] = d[k];
        }
    } else {
#pragma unroll
        for (int k = 0; k < ITERS; k++) {
            int i = base + k * TPB;
            if (i < n4) {
                ulonglong2 d = in[i];
                d.x = ffma2(d.x, mul01, add01);
                d.y = ffma2(d.y, mul23, add23);
                out[i] = d;
            }
        }
    }
}

extern "C" void kernel_launch(void* const* d_in, const int* in_sizes, int n_in,
                              void* d_out, int out_size) {
    const float* data   = (const float*)d_in[0];
    const float* params = (const float*)d_in[1];
    if (n_in >= 2 && in_sizes[0] == 2 * 4 * POINTS) {  // defensive order swap
        data   = (const float*)d_in[1];
        params = (const float*)d_in[0];
    }

    int n4 = out_size / 4;                      // 4,194,304 float4s
    int per_block = TPB * ITERS;                // 2048 float4s per block
    int blocks = (n4 + per_block - 1) / per_block;  // 2048 blocks
    foil_kernel<<<blocks, TPB>>>((const ulonglong2*)data, (ulonglong2*)d_out,
                                 params, n4);
}